// round 1
// baseline (speedup 1.0000x reference)
#include <cuda_runtime.h>
#include <math.h>

// Problem shapes (fixed for this dataset row)
#define NTOK 16384          // B*T = 8*2048
#define CDIM 256
#define HDIM 682
#define NEXP 8
#define BM 64               // M tile (tokens/slots)
#define BN 64               // N tile
#define BK 32               // K tile
#define PADDED_MAX (NTOK*2 + NEXP*BM)   // 33280
#define MTILES (PADDED_MAX / BM)        // 520

// ---------------- device scratch (allocation-free: __device__ globals) ----
__device__ int   d_counts[NEXP];
__device__ int   d_poff[NEXP + 1];      // padded exclusive offsets
__device__ int   d_cursor[NEXP];
__device__ int   d_slot_token[PADDED_MAX];       // token id per slot, -1 = pad
__device__ int   d_tok_slot[NTOK * 2];           // slot position per (token,k)
__device__ float d_tok_gate[NTOK * 2];
__device__ int   d_tok_expert[NTOK * 2];
__device__ float d_h[(size_t)PADDED_MAX * HDIM]; // swiglu activations
__device__ float d_yv[(size_t)PADDED_MAX * CDIM];// per-slot expert output

// ---------------- K0: zero counts (must run every launch for graph replay) -
__global__ void k_zero() {
    if (threadIdx.x < NEXP) d_counts[threadIdx.x] = 0;
}

// ---------------- K1: router (softmax over 8, top-2, renormalized gates) --
__global__ void k_router(const float* __restrict__ x,
                         const float* __restrict__ rw) {
    __shared__ float s_rw[NEXP * CDIM];
    for (int i = threadIdx.x; i < NEXP * CDIM; i += blockDim.x) s_rw[i] = rw[i];
    __syncthreads();

    int warp = threadIdx.x >> 5, lane = threadIdx.x & 31;
    int n = blockIdx.x * 8 + warp;
    if (n >= NTOK) return;
    const float* xr = x + n * CDIM;

    float acc[NEXP];
#pragma unroll
    for (int e = 0; e < NEXP; e++) acc[e] = 0.f;
    for (int c = lane; c < CDIM; c += 32) {
        float xv = xr[c];
#pragma unroll
        for (int e = 0; e < NEXP; e++) acc[e] = fmaf(xv, s_rw[e * CDIM + c], acc[e]);
    }
#pragma unroll
    for (int e = 0; e < NEXP; e++) {
#pragma unroll
        for (int off = 16; off; off >>= 1)
            acc[e] += __shfl_down_sync(0xffffffffu, acc[e], off);
    }
    if (lane != 0) return;

    float m = acc[0];
#pragma unroll
    for (int e = 1; e < NEXP; e++) m = fmaxf(m, acc[e]);
    float p[NEXP]; float s = 0.f;
#pragma unroll
    for (int e = 0; e < NEXP; e++) { p[e] = expf(acc[e] - m); s += p[e]; }
    float inv = 1.f / s;
#pragma unroll
    for (int e = 0; e < NEXP; e++) p[e] *= inv;

    int i0 = 0;
#pragma unroll
    for (int e = 1; e < NEXP; e++) if (p[e] > p[i0]) i0 = e;
    int i1 = (i0 == 0) ? 1 : 0;
#pragma unroll
    for (int e = 0; e < NEXP; e++) if (e != i0 && p[e] > p[i1]) i1 = e;

    float denom = p[i0] + p[i1] + 1e-9f;
    d_tok_expert[2 * n + 0] = i0;
    d_tok_expert[2 * n + 1] = i1;
    d_tok_gate[2 * n + 0] = p[i0] / denom;
    d_tok_gate[2 * n + 1] = p[i1] / denom;
    atomicAdd(&d_counts[i0], 1);
    atomicAdd(&d_counts[i1], 1);
}

// ---------------- K2: padded scan + slot init ----------------------------
__global__ void k_setup() {
    for (int i = threadIdx.x; i < PADDED_MAX; i += blockDim.x)
        d_slot_token[i] = -1;
    __syncthreads();
    if (threadIdx.x == 0) {
        int off = 0;
        for (int e = 0; e < NEXP; e++) {
            d_poff[e] = off;
            d_cursor[e] = off;
            off += ((d_counts[e] + BM - 1) / BM) * BM;
        }
        d_poff[NEXP] = off;
    }
}

// ---------------- K3: scatter tokens into per-expert slot regions --------
__global__ void k_scatter() {
    int i = blockIdx.x * blockDim.x + threadIdx.x;
    if (i >= NTOK * 2) return;
    int n = i >> 1;
    int e = d_tok_expert[i];
    int pos = atomicAdd(&d_cursor[e], 1);
    d_slot_token[pos] = n;
    d_tok_slot[i] = pos;
}

// ---------------- K4: GEMM1 fused (h = silu(x w1^T) * (x w3^T)) ----------
// Tile: BM x BN, K=256. Two B operands (w1,w3), dual accumulators.
__global__ void __launch_bounds__(256) k_gemm1(const float* __restrict__ x,
                                               const float* __restrict__ w1,
                                               const float* __restrict__ w3) {
    __shared__ float As[BK][BM + 4];
    __shared__ float B1s[BK][BN + 4];
    __shared__ float B3s[BK][BN + 4];
    __shared__ int s_tok[BM];

    int sbase = blockIdx.x * BM;
    int total = d_poff[NEXP];
    if (sbase >= total) return;
    int e = 0;
#pragma unroll
    for (int q = 0; q < NEXP - 1; q++) if (d_poff[q + 1] <= sbase) e = q + 1;

    int n0 = blockIdx.y * BN;
    int tid = threadIdx.x;
    if (tid < BM) s_tok[tid] = d_slot_token[sbase + tid];

    int tx = tid & 15, ty = tid >> 4;
    float acc1[4][4], acc3[4][4];
#pragma unroll
    for (int i = 0; i < 4; i++)
#pragma unroll
        for (int j = 0; j < 4; j++) { acc1[i][j] = 0.f; acc3[i][j] = 0.f; }

    const float* w1e = w1 + (size_t)e * HDIM * CDIM;
    const float* w3e = w3 + (size_t)e * HDIM * CDIM;

    for (int k0 = 0; k0 < CDIM; k0 += BK) {
        __syncthreads();
        // load A (gathered tokens) and B1/B3 (weight rows, masked by HDIM)
#pragma unroll
        for (int i = tid; i < BM * BK; i += 256) {
            int m = i >> 5, k = i & 31;
            int tok = s_tok[m];
            As[k][m] = (tok >= 0) ? x[tok * CDIM + k0 + k] : 0.f;
            int row = n0 + m;
            if (row < HDIM) {
                B1s[k][m] = w1e[row * CDIM + k0 + k];
                B3s[k][m] = w3e[row * CDIM + k0 + k];
            } else {
                B1s[k][m] = 0.f; B3s[k][m] = 0.f;
            }
        }
        __syncthreads();
#pragma unroll
        for (int kk = 0; kk < BK; kk++) {
            float4 av  = *(const float4*)&As[kk][ty * 4];
            float4 b1v = *(const float4*)&B1s[kk][tx * 4];
            float4 b3v = *(const float4*)&B3s[kk][tx * 4];
            float a[4] = {av.x, av.y, av.z, av.w};
            float b1[4] = {b1v.x, b1v.y, b1v.z, b1v.w};
            float b3[4] = {b3v.x, b3v.y, b3v.z, b3v.w};
#pragma unroll
            for (int i = 0; i < 4; i++)
#pragma unroll
                for (int j = 0; j < 4; j++) {
                    acc1[i][j] = fmaf(a[i], b1[j], acc1[i][j]);
                    acc3[i][j] = fmaf(a[i], b3[j], acc3[i][j]);
                }
        }
    }

    // epilogue: silu(h1)*h3 -> d_h
#pragma unroll
    for (int i = 0; i < 4; i++) {
        int m = ty * 4 + i;
#pragma unroll
        for (int j = 0; j < 4; j++) {
            int hc = n0 + tx * 4 + j;
            if (hc < HDIM) {
                float a = acc1[i][j];
                float sg = 1.f / (1.f + expf(-a));
                d_h[(size_t)(sbase + m) * HDIM + hc] = a * sg * acc3[i][j];
            }
        }
    }
}

// ---------------- K5: GEMM2 (y = h w2^T), K=682 with masked loads --------
__global__ void __launch_bounds__(256) k_gemm2(const float* __restrict__ w2) {
    __shared__ float As[BK][BM + 4];
    __shared__ float Bs[BK][BN + 4];

    int sbase = blockIdx.x * BM;
    int total = d_poff[NEXP];
    if (sbase >= total) return;
    int e = 0;
#pragma unroll
    for (int q = 0; q < NEXP - 1; q++) if (d_poff[q + 1] <= sbase) e = q + 1;

    int n0 = blockIdx.y * BN;
    int tid = threadIdx.x;
    int tx = tid & 15, ty = tid >> 4;
    float acc[4][4];
#pragma unroll
    for (int i = 0; i < 4; i++)
#pragma unroll
        for (int j = 0; j < 4; j++) acc[i][j] = 0.f;

    const float* w2e = w2 + (size_t)e * CDIM * HDIM;

    for (int k0 = 0; k0 < HDIM; k0 += BK) {
        __syncthreads();
#pragma unroll
        for (int i = tid; i < BM * BK; i += 256) {
            int m = i >> 5, k = i & 31;
            int kg = k0 + k;
            As[k][m] = (kg < HDIM) ? d_h[(size_t)(sbase + m) * HDIM + kg] : 0.f;
            Bs[k][m] = (kg < HDIM) ? w2e[(n0 + m) * HDIM + kg] : 0.f;
        }
        __syncthreads();
#pragma unroll
        for (int kk = 0; kk < BK; kk++) {
            float4 av = *(const float4*)&As[kk][ty * 4];
            float4 bv = *(const float4*)&Bs[kk][tx * 4];
            float a[4] = {av.x, av.y, av.z, av.w};
            float b[4] = {bv.x, bv.y, bv.z, bv.w};
#pragma unroll
            for (int i = 0; i < 4; i++)
#pragma unroll
                for (int j = 0; j < 4; j++)
                    acc[i][j] = fmaf(a[i], b[j], acc[i][j]);
        }
    }

#pragma unroll
    for (int i = 0; i < 4; i++) {
        int m = ty * 4 + i;
#pragma unroll
        for (int j = 0; j < 4; j++) {
            int c = n0 + tx * 4 + j;
            d_yv[(size_t)(sbase + m) * CDIM + c] = acc[i][j];
        }
    }
}

// ---------------- K6: combine out[n] = g0*y[slot0] + g1*y[slot1] ---------
__global__ void k_combine(float* __restrict__ out) {
    int idx = blockIdx.x * blockDim.x + threadIdx.x;   // NTOK * (CDIM/4)
    if (idx >= NTOK * (CDIM / 4)) return;
    int n = idx >> 6;
    int c4 = idx & 63;
    int s0 = d_tok_slot[2 * n + 0], s1 = d_tok_slot[2 * n + 1];
    float g0 = d_tok_gate[2 * n + 0], g1 = d_tok_gate[2 * n + 1];
    float4 y0 = *(const float4*)&d_yv[(size_t)s0 * CDIM + c4 * 4];
    float4 y1 = *(const float4*)&d_yv[(size_t)s1 * CDIM + c4 * 4];
    float4 o;
    o.x = g0 * y0.x + g1 * y1.x;
    o.y = g0 * y0.y + g1 * y1.y;
    o.z = g0 * y0.z + g1 * y1.z;
    o.w = g0 * y0.w + g1 * y1.w;
    *(float4*)&out[(size_t)n * CDIM + c4 * 4] = o;
}

// ---------------- launch --------------------------------------------------
extern "C" void kernel_launch(void* const* d_in, const int* in_sizes, int n_in,
                              void* d_out, int out_size) {
    const float* x  = (const float*)d_in[0];
    const float* rw = (const float*)d_in[1];
    const float* w1 = (const float*)d_in[2];
    const float* w2 = (const float*)d_in[3];
    const float* w3 = (const float*)d_in[4];
    float* out = (float*)d_out;

    k_zero<<<1, 32>>>();
    k_router<<<NTOK / 8, 256>>>(x, rw);
    k_setup<<<1, 256>>>();
    k_scatter<<<(NTOK * 2 + 255) / 256, 256>>>();

    dim3 g1(MTILES, (HDIM + BN - 1) / BN);
    k_gemm1<<<g1, 256>>>(x, w1, w3);

    dim3 g2(MTILES, CDIM / BN);
    k_gemm2<<<g2, 256>>>(w2);

    k_combine<<<(NTOK * (CDIM / 4) + 255) / 256, 256>>>(out);
}

// round 3
// speedup vs baseline: 2.8893x; 2.8893x over previous
#include <cuda_runtime.h>
#include <math.h>
#include <stdint.h>

// Problem shapes (fixed)
#define NTOK 16384
#define CDIM 256
#define HDIM 682
#define HPAD 704            // 22 chunks of 32
#define NEXP 8
#define TM   128            // block M tile (slots)
#define TN   64             // block N tile
#define BK   32
#define PADDED_MAX (NTOK*2 + NEXP*TM)   // 33792
#define MTILES (PADDED_MAX / TM)        // 264

// ---------------- device scratch ----------------
__device__ int   d_counts[NEXP];
__device__ int   d_poff[NEXP + 1];
__device__ int   d_cursor[NEXP];
__device__ int   d_slot_token[PADDED_MAX];
__device__ int   d_tok_slot[NTOK * 2];
__device__ float d_tok_gate[NTOK * 2];
__device__ int   d_tok_expert[NTOK * 2];
__device__ float d_h[(size_t)PADDED_MAX * HPAD];
__device__ float d_yv[(size_t)PADDED_MAX * CDIM];

// ---------------- helpers ----------------
__device__ __forceinline__ uint32_t tf32u(float f) {
    uint32_t u;
    asm("cvt.rna.tf32.f32 %0, %1;" : "=r"(u) : "f"(f));
    return u;
}
__device__ __forceinline__ float tf32f(float f) { return __uint_as_float(tf32u(f)); }

__device__ __forceinline__ void mma_tf32(float c[4], uint32_t a0, uint32_t a1,
                                         uint32_t a2, uint32_t a3,
                                         uint32_t b0, uint32_t b1) {
    asm volatile(
        "mma.sync.aligned.m16n8k8.row.col.f32.tf32.tf32.f32 "
        "{%0,%1,%2,%3}, {%4,%5,%6,%7}, {%8,%9}, {%0,%1,%2,%3};"
        : "+f"(c[0]), "+f"(c[1]), "+f"(c[2]), "+f"(c[3])
        : "r"(a0), "r"(a1), "r"(a2), "r"(a3), "r"(b0), "r"(b1));
}

// ---------------- routing ----------------
__global__ void k_zero() { if (threadIdx.x < NEXP) d_counts[threadIdx.x] = 0; }

__global__ void k_router(const float* __restrict__ x, const float* __restrict__ rw) {
    __shared__ float s_rw[NEXP * CDIM];
    for (int i = threadIdx.x; i < NEXP * CDIM; i += blockDim.x) s_rw[i] = rw[i];
    __syncthreads();
    int warp = threadIdx.x >> 5, lane = threadIdx.x & 31;
    int n = blockIdx.x * 8 + warp;
    if (n >= NTOK) return;
    const float* xr = x + n * CDIM;
    float acc[NEXP];
#pragma unroll
    for (int e = 0; e < NEXP; e++) acc[e] = 0.f;
    for (int c = lane; c < CDIM; c += 32) {
        float xv = xr[c];
#pragma unroll
        for (int e = 0; e < NEXP; e++) acc[e] = fmaf(xv, s_rw[e * CDIM + c], acc[e]);
    }
#pragma unroll
    for (int e = 0; e < NEXP; e++)
#pragma unroll
        for (int off = 16; off; off >>= 1)
            acc[e] += __shfl_down_sync(0xffffffffu, acc[e], off);
    if (lane != 0) return;
    float m = acc[0];
#pragma unroll
    for (int e = 1; e < NEXP; e++) m = fmaxf(m, acc[e]);
    float p[NEXP], s = 0.f;
#pragma unroll
    for (int e = 0; e < NEXP; e++) { p[e] = expf(acc[e] - m); s += p[e]; }
    float inv = 1.f / s;
#pragma unroll
    for (int e = 0; e < NEXP; e++) p[e] *= inv;
    int i0 = 0;
#pragma unroll
    for (int e = 1; e < NEXP; e++) if (p[e] > p[i0]) i0 = e;
    int i1 = (i0 == 0) ? 1 : 0;
#pragma unroll
    for (int e = 0; e < NEXP; e++) if (e != i0 && p[e] > p[i1]) i1 = e;
    float denom = p[i0] + p[i1] + 1e-9f;
    d_tok_expert[2 * n + 0] = i0;
    d_tok_expert[2 * n + 1] = i1;
    d_tok_gate[2 * n + 0] = p[i0] / denom;
    d_tok_gate[2 * n + 1] = p[i1] / denom;
    atomicAdd(&d_counts[i0], 1);
    atomicAdd(&d_counts[i1], 1);
}

__global__ void k_init_slots() {
    int i = blockIdx.x * blockDim.x + threadIdx.x;
    if (i < PADDED_MAX) d_slot_token[i] = -1;
}

__global__ void k_setup() {
    if (threadIdx.x == 0) {
        int off = 0;
        for (int e = 0; e < NEXP; e++) {
            d_poff[e] = off;
            d_cursor[e] = off;
            off += ((d_counts[e] + TM - 1) / TM) * TM;
        }
        d_poff[NEXP] = off;
    }
}

__global__ void k_scatter() {
    int i = blockIdx.x * blockDim.x + threadIdx.x;
    if (i >= NTOK * 2) return;
    int n = i >> 1;
    int e = d_tok_expert[i];
    int pos = atomicAdd(&d_cursor[e], 1);
    d_slot_token[pos] = n;
    d_tok_slot[i] = pos;
}

// ---------------- GEMM1: h = silu(x w1^T) * (x w3^T), mma.sync tf32 ------
// 256 thr = 8 warps (4 along M x 2 along N). Block tile 128x64, warp 32x32.
__global__ void __launch_bounds__(256) k_gemm1_mma(const float* __restrict__ x,
                                                   const float* __restrict__ w1,
                                                   const float* __restrict__ w3) {
    __shared__ float As[TM][BK + 1];
    __shared__ float B1s[TN][BK + 1];
    __shared__ float B3s[TN][BK + 1];
    __shared__ int s_tok[TM];

    int sbase = blockIdx.x * TM;
    int total = d_poff[NEXP];
    if (sbase >= total) return;
    int e = 0;
#pragma unroll
    for (int q = 0; q < NEXP - 1; q++) if (d_poff[q + 1] <= sbase) e = q + 1;
    int n0 = blockIdx.y * TN;

    int tid = threadIdx.x, lane = tid & 31, wid = tid >> 5;
    int wm = wid >> 1, wn = wid & 1;           // warp grid 4x2
    if (tid < TM) s_tok[tid] = d_slot_token[sbase + tid];
    __syncthreads();

    const float* w1e = w1 + (size_t)e * HDIM * CDIM;
    const float* w3e = w3 + (size_t)e * HDIM * CDIM;

    float c1[2][4][4], c3[2][4][4];
#pragma unroll
    for (int mt = 0; mt < 2; mt++)
#pragma unroll
        for (int nt = 0; nt < 4; nt++)
#pragma unroll
            for (int r = 0; r < 4; r++) { c1[mt][nt][r] = 0.f; c3[mt][nt][r] = 0.f; }

    int lr = lane >> 2, lc = lane & 3;

    for (int k0 = 0; k0 < CDIM; k0 += BK) {
        // A: 128x32 fp32 (gathered); 16 float loads/thread via float4
#pragma unroll
        for (int i = tid; i < TM * (BK / 4); i += 256) {
            int m = i >> 3, f4 = i & 7;
            int tok = s_tok[m];
            float4 v = make_float4(0.f, 0.f, 0.f, 0.f);
            if (tok >= 0) v = *(const float4*)&x[(size_t)tok * CDIM + k0 + f4 * 4];
            As[m][f4 * 4 + 0] = tf32f(v.x);
            As[m][f4 * 4 + 1] = tf32f(v.y);
            As[m][f4 * 4 + 2] = tf32f(v.z);
            As[m][f4 * 4 + 3] = tf32f(v.w);
        }
        // B1/B3: 64x32 each
#pragma unroll
        for (int i = tid; i < TN * (BK / 4); i += 256) {
            int nn = i >> 3, f4 = i & 7;
            int hr = n0 + nn;
            float4 v1 = make_float4(0.f, 0.f, 0.f, 0.f), v3 = v1;
            if (hr < HDIM) {
                v1 = *(const float4*)&w1e[(size_t)hr * CDIM + k0 + f4 * 4];
                v3 = *(const float4*)&w3e[(size_t)hr * CDIM + k0 + f4 * 4];
            }
            B1s[nn][f4 * 4 + 0] = tf32f(v1.x); B3s[nn][f4 * 4 + 0] = tf32f(v3.x);
            B1s[nn][f4 * 4 + 1] = tf32f(v1.y); B3s[nn][f4 * 4 + 1] = tf32f(v3.y);
            B1s[nn][f4 * 4 + 2] = tf32f(v1.z); B3s[nn][f4 * 4 + 2] = tf32f(v3.z);
            B1s[nn][f4 * 4 + 3] = tf32f(v1.w); B3s[nn][f4 * 4 + 3] = tf32f(v3.w);
        }
        __syncthreads();
#pragma unroll
        for (int ks = 0; ks < BK / 8; ks++) {
            int k = ks * 8;
            uint32_t a[2][4];
#pragma unroll
            for (int mt = 0; mt < 2; mt++) {
                int row = wm * 32 + mt * 16 + lr;
                a[mt][0] = __float_as_uint(As[row][k + lc]);
                a[mt][1] = __float_as_uint(As[row + 8][k + lc]);
                a[mt][2] = __float_as_uint(As[row][k + 4 + lc]);
                a[mt][3] = __float_as_uint(As[row + 8][k + 4 + lc]);
            }
#pragma unroll
            for (int nt = 0; nt < 4; nt++) {
                int col = wn * 32 + nt * 8 + lr;
                uint32_t b10 = __float_as_uint(B1s[col][k + lc]);
                uint32_t b11 = __float_as_uint(B1s[col][k + 4 + lc]);
                uint32_t b30 = __float_as_uint(B3s[col][k + lc]);
                uint32_t b31 = __float_as_uint(B3s[col][k + 4 + lc]);
#pragma unroll
                for (int mt = 0; mt < 2; mt++) {
                    mma_tf32(c1[mt][nt], a[mt][0], a[mt][1], a[mt][2], a[mt][3], b10, b11);
                    mma_tf32(c3[mt][nt], a[mt][0], a[mt][1], a[mt][2], a[mt][3], b30, b31);
                }
            }
        }
        __syncthreads();
    }

    // Epilogue: silu(c1)*c3 -> d_h (pad cols [HDIM,HPAD) get exact zeros
    // because B was zero-masked there and A pad rows are zero)
#pragma unroll
    for (int mt = 0; mt < 2; mt++) {
#pragma unroll
        for (int nt = 0; nt < 4; nt++) {
#pragma unroll
            for (int half = 0; half < 2; half++) {
                int row = sbase + wm * 32 + mt * 16 + lr + half * 8;
                int col = n0 + wn * 32 + nt * 8 + lc * 2;
                float a0 = c1[mt][nt][half * 2 + 0], a1 = c1[mt][nt][half * 2 + 1];
                float b0 = c3[mt][nt][half * 2 + 0], b1 = c3[mt][nt][half * 2 + 1];
                float2 o;
                o.x = a0 / (1.f + expf(-a0)) * b0;
                o.y = a1 / (1.f + expf(-a1)) * b1;
                *(float2*)&d_h[(size_t)row * HPAD + col] = o;
            }
        }
    }
}

// ---------------- GEMM2: y = h w2^T, mma.sync tf32 -----------------------
__global__ void __launch_bounds__(256) k_gemm2_mma(const float* __restrict__ w2) {
    __shared__ float As[TM][BK + 1];
    __shared__ float Bs[TN][BK + 1];

    int sbase = blockIdx.x * TM;
    int total = d_poff[NEXP];
    if (sbase >= total) return;
    int e = 0;
#pragma unroll
    for (int q = 0; q < NEXP - 1; q++) if (d_poff[q + 1] <= sbase) e = q + 1;
    int n0 = blockIdx.y * TN;

    int tid = threadIdx.x, lane = tid & 31, wid = tid >> 5;
    int wm = wid >> 1, wn = wid & 1;
    const float* w2e = w2 + (size_t)e * CDIM * HDIM;

    float c[2][4][4];
#pragma unroll
    for (int mt = 0; mt < 2; mt++)
#pragma unroll
        for (int nt = 0; nt < 4; nt++)
#pragma unroll
            for (int r = 0; r < 4; r++) c[mt][nt][r] = 0.f;

    int lr = lane >> 2, lc = lane & 3;

    for (int k0 = 0; k0 < HPAD; k0 += BK) {
        // A: d_h rows (zero-padded to HPAD already)
#pragma unroll
        for (int i = tid; i < TM * (BK / 4); i += 256) {
            int m = i >> 3, f4 = i & 7;
            float4 v = *(const float4*)&d_h[(size_t)(sbase + m) * HPAD + k0 + f4 * 4];
            As[m][f4 * 4 + 0] = tf32f(v.x);
            As[m][f4 * 4 + 1] = tf32f(v.y);
            As[m][f4 * 4 + 2] = tf32f(v.z);
            As[m][f4 * 4 + 3] = tf32f(v.w);
        }
        // B: w2 rows length 682, scalar masked loads
#pragma unroll
        for (int i = tid; i < TN * BK; i += 256) {
            int nn = i >> 5, kk = i & 31;
            int kg = k0 + kk;
            float v = (kg < HDIM) ? w2e[(size_t)(n0 + nn) * HDIM + kg] : 0.f;
            Bs[nn][kk] = tf32f(v);
        }
        __syncthreads();
#pragma unroll
        for (int ks = 0; ks < BK / 8; ks++) {
            int k = ks * 8;
            uint32_t a[2][4];
#pragma unroll
            for (int mt = 0; mt < 2; mt++) {
                int row = wm * 32 + mt * 16 + lr;
                a[mt][0] = __float_as_uint(As[row][k + lc]);
                a[mt][1] = __float_as_uint(As[row + 8][k + lc]);
                a[mt][2] = __float_as_uint(As[row][k + 4 + lc]);
                a[mt][3] = __float_as_uint(As[row + 8][k + 4 + lc]);
            }
#pragma unroll
            for (int nt = 0; nt < 4; nt++) {
                int col = wn * 32 + nt * 8 + lr;
                uint32_t b0 = __float_as_uint(Bs[col][k + lc]);
                uint32_t b1 = __float_as_uint(Bs[col][k + 4 + lc]);
#pragma unroll
                for (int mt = 0; mt < 2; mt++)
                    mma_tf32(c[mt][nt], a[mt][0], a[mt][1], a[mt][2], a[mt][3], b0, b1);
            }
        }
        __syncthreads();
    }

#pragma unroll
    for (int mt = 0; mt < 2; mt++) {
#pragma unroll
        for (int nt = 0; nt < 4; nt++) {
#pragma unroll
            for (int half = 0; half < 2; half++) {
                int row = sbase + wm * 32 + mt * 16 + lr + half * 8;
                int col = n0 + wn * 32 + nt * 8 + lc * 2;
                float2 o = make_float2(c[mt][nt][half * 2 + 0], c[mt][nt][half * 2 + 1]);
                *(float2*)&d_yv[(size_t)row * CDIM + col] = o;
            }
        }
    }
}

// ---------------- combine ----------------
__global__ void k_combine(float* __restrict__ out) {
    int idx = blockIdx.x * blockDim.x + threadIdx.x;
    if (idx >= NTOK * (CDIM / 4)) return;
    int n = idx >> 6, c4 = idx & 63;
    int s0 = d_tok_slot[2 * n + 0], s1 = d_tok_slot[2 * n + 1];
    float g0 = d_tok_gate[2 * n + 0], g1 = d_tok_gate[2 * n + 1];
    float4 y0 = *(const float4*)&d_yv[(size_t)s0 * CDIM + c4 * 4];
    float4 y1 = *(const float4*)&d_yv[(size_t)s1 * CDIM + c4 * 4];
    float4 o;
    o.x = g0 * y0.x + g1 * y1.x;
    o.y = g0 * y0.y + g1 * y1.y;
    o.z = g0 * y0.z + g1 * y1.z;
    o.w = g0 * y0.w + g1 * y1.w;
    *(float4*)&out[(size_t)n * CDIM + c4 * 4] = o;
}

// ---------------- launch ----------------
extern "C" void kernel_launch(void* const* d_in, const int* in_sizes, int n_in,
                              void* d_out, int out_size) {
    const float* x  = (const float*)d_in[0];
    const float* rw = (const float*)d_in[1];
    const float* w1 = (const float*)d_in[2];
    const float* w2 = (const float*)d_in[3];
    const float* w3 = (const float*)d_in[4];
    float* out = (float*)d_out;

    k_zero<<<1, 32>>>();
    k_router<<<NTOK / 8, 256>>>(x, rw);
    k_init_slots<<<(PADDED_MAX + 255) / 256, 256>>>();
    k_setup<<<1, 32>>>();
    k_scatter<<<(NTOK * 2 + 255) / 256, 256>>>();

    dim3 g1(MTILES, HPAD / TN);              // 264 x 11
    k_gemm1_mma<<<g1, 256>>>(x, w1, w3);

    dim3 g2(MTILES, CDIM / TN);              // 264 x 4
    k_gemm2_mma<<<g2, 256>>>(w2);

    k_combine<<<(NTOK * (CDIM / 4) + 255) / 256, 256>>>(out);
}

// round 5
// speedup vs baseline: 6.4843x; 2.2442x over previous
#include <cuda_runtime.h>
#include <math.h>
#include <stdint.h>

// Problem shapes (fixed)
#define NTOK 16384
#define CDIM 256
#define HDIM 682
#define HPAD 704            // 22 chunks of 32
#define NEXP 8
#define TM   128
#define TN   64
#define BK   32
#define PADDED_MAX (NTOK*2 + NEXP*TM)   // 33792
#define MTILES (PADDED_MAX / TM)        // 264
#define WELEM (NEXP * HDIM * CDIM)      // 1396736

// ---------------- device scratch ----------------
__device__ int   d_counts[NEXP];
__device__ int   d_poff[NEXP + 1];
__device__ int   d_cursor[NEXP];
__device__ int   d_slot_token[PADDED_MAX];
__device__ int   d_tok_slot[NTOK * 2];
__device__ float d_tok_gate[NTOK * 2];
__device__ int   d_tok_expert[NTOK * 2];
__device__ float d_h[(size_t)PADDED_MAX * HPAD];
__device__ float d_yv[(size_t)PADDED_MAX * CDIM];
// tf32-prerounded operand copies (accessed directly as device globals)
__device__ float d_xc[(size_t)NTOK * CDIM];
__device__ float d_w1c[WELEM];
__device__ float d_w3c[WELEM];
__device__ float d_w2c[WELEM];

// ---------------- helpers ----------------
__device__ __forceinline__ uint32_t smem_u32(const void* p) {
    uint32_t a;
    asm("{ .reg .u64 t; cvta.to.shared.u64 t, %1; cvt.u32.u64 %0, t; }" : "=r"(a) : "l"(p));
    return a;
}
__device__ __forceinline__ float tf32f(float f) {
    uint32_t u;
    asm("cvt.rna.tf32.f32 %0, %1;" : "=r"(u) : "f"(f));
    return __uint_as_float(u);
}
__device__ __forceinline__ void mma_tf32(float c[4], uint32_t a0, uint32_t a1,
                                         uint32_t a2, uint32_t a3,
                                         uint32_t b0, uint32_t b1) {
    asm volatile(
        "mma.sync.aligned.m16n8k8.row.col.f32.tf32.tf32.f32 "
        "{%0,%1,%2,%3}, {%4,%5,%6,%7}, {%8,%9}, {%0,%1,%2,%3};"
        : "+f"(c[0]), "+f"(c[1]), "+f"(c[2]), "+f"(c[3])
        : "r"(a0), "r"(a1), "r"(a2), "r"(a3), "r"(b0), "r"(b1));
}
__device__ __forceinline__ void cp16(uint32_t dst, const void* src, uint32_t bytes) {
    asm volatile("cp.async.cg.shared.global [%0], [%1], 16, %2;"
                 :: "r"(dst), "l"(src), "r"(bytes) : "memory");
}
__device__ __forceinline__ void cp8(uint32_t dst, const void* src, uint32_t bytes) {
    asm volatile("cp.async.ca.shared.global [%0], [%1], 8, %2;"
                 :: "r"(dst), "l"(src), "r"(bytes) : "memory");
}
#define CP_COMMIT() asm volatile("cp.async.commit_group;" ::: "memory")
#define CP_WAIT(n)  asm volatile("cp.async.wait_group %0;" :: "n"(n) : "memory")

// SMEM float offsets (row pitch 36 floats = 144B, 16B aligned, conflict-free)
#define G1_A(st)  ((st) * 4608)
#define G1_B1(st) (9216 + (st) * 2304)
#define G1_B3(st) (13824 + (st) * 2304)
#define G1_BYTES  73728
#define G2_A(st)  ((st) * 4608)
#define G2_B(st)  (9216 + (st) * 2304)
#define G2_BYTES  55296

// ---------------- routing (+ x pre-round folded in) ----------------
__global__ void k_zero() { if (threadIdx.x < NEXP) d_counts[threadIdx.x] = 0; }

__global__ void k_router(const float* __restrict__ x, const float* __restrict__ rw) {
    __shared__ float s_rw[NEXP * CDIM];
    for (int i = threadIdx.x; i < NEXP * CDIM; i += blockDim.x) s_rw[i] = rw[i];
    __syncthreads();
    int warp = threadIdx.x >> 5, lane = threadIdx.x & 31;
    int n = blockIdx.x * 8 + warp;
    if (n >= NTOK) return;
    const float* xr = x + (size_t)n * CDIM;
    float acc[NEXP];
#pragma unroll
    for (int e = 0; e < NEXP; e++) acc[e] = 0.f;
    for (int c = lane; c < CDIM; c += 32) {
        float xv = xr[c];
        d_xc[(size_t)n * CDIM + c] = tf32f(xv);   // pre-rounded copy for GEMM1
#pragma unroll
        for (int e = 0; e < NEXP; e++) acc[e] = fmaf(xv, s_rw[e * CDIM + c], acc[e]);
    }
#pragma unroll
    for (int e = 0; e < NEXP; e++)
#pragma unroll
        for (int off = 16; off; off >>= 1)
            acc[e] += __shfl_down_sync(0xffffffffu, acc[e], off);
    if (lane != 0) return;
    float m = acc[0];
#pragma unroll
    for (int e = 1; e < NEXP; e++) m = fmaxf(m, acc[e]);
    float p[NEXP], s = 0.f;
#pragma unroll
    for (int e = 0; e < NEXP; e++) { p[e] = expf(acc[e] - m); s += p[e]; }
    float inv = 1.f / s;
#pragma unroll
    for (int e = 0; e < NEXP; e++) p[e] *= inv;
    int i0 = 0;
#pragma unroll
    for (int e = 1; e < NEXP; e++) if (p[e] > p[i0]) i0 = e;
    int i1 = (i0 == 0) ? 1 : 0;
#pragma unroll
    for (int e = 0; e < NEXP; e++) if (e != i0 && p[e] > p[i1]) i1 = e;
    float denom = p[i0] + p[i1] + 1e-9f;
    d_tok_expert[2 * n + 0] = i0;
    d_tok_expert[2 * n + 1] = i1;
    d_tok_gate[2 * n + 0] = p[i0] / denom;
    d_tok_gate[2 * n + 1] = p[i1] / denom;
    atomicAdd(&d_counts[i0], 1);
    atomicAdd(&d_counts[i1], 1);
}

// pre-round all three weight tensors to tf32 (one pass)
__global__ void k_cvt_w(const float* __restrict__ w1, const float* __restrict__ w3,
                        const float* __restrict__ w2) {
    int i = blockIdx.x * blockDim.x + threadIdx.x;
    if (i >= WELEM / 4) return;
    float4 a = ((const float4*)w1)[i];
    float4 b = ((const float4*)w3)[i];
    float4 c = ((const float4*)w2)[i];
    ((float4*)d_w1c)[i] = make_float4(tf32f(a.x), tf32f(a.y), tf32f(a.z), tf32f(a.w));
    ((float4*)d_w3c)[i] = make_float4(tf32f(b.x), tf32f(b.y), tf32f(b.z), tf32f(b.w));
    ((float4*)d_w2c)[i] = make_float4(tf32f(c.x), tf32f(c.y), tf32f(c.z), tf32f(c.w));
}

__global__ void k_init_slots() {
    int i = blockIdx.x * blockDim.x + threadIdx.x;
    if (i < PADDED_MAX) d_slot_token[i] = -1;
}

__global__ void k_setup() {
    if (threadIdx.x == 0) {
        int off = 0;
        for (int e = 0; e < NEXP; e++) {
            d_poff[e] = off;
            d_cursor[e] = off;
            off += ((d_counts[e] + TM - 1) / TM) * TM;
        }
        d_poff[NEXP] = off;
    }
}

__global__ void k_scatter() {
    int i = blockIdx.x * blockDim.x + threadIdx.x;
    if (i >= NTOK * 2) return;
    int n = i >> 1;
    int e = d_tok_expert[i];
    int pos = atomicAdd(&d_cursor[e], 1);
    d_slot_token[pos] = n;
    d_tok_slot[i] = pos;
}

// ---------------- GEMM1: h = silu(x w1^T) * (x w3^T) ---------------------
__global__ void __launch_bounds__(256) k_gemm1_mma() {
    extern __shared__ float smem[];
    __shared__ int s_tok[TM];
    uint32_t sb = smem_u32(smem);

    int sbase = blockIdx.x * TM;
    int total = d_poff[NEXP];
    if (sbase >= total) return;
    int e = 0;
#pragma unroll
    for (int q = 0; q < NEXP - 1; q++) if (d_poff[q + 1] <= sbase) e = q + 1;
    int n0 = blockIdx.y * TN;

    int tid = threadIdx.x, lane = tid & 31, wid = tid >> 5;
    int wm = wid >> 1, wn = wid & 1;
    if (tid < TM) s_tok[tid] = d_slot_token[sbase + tid];
    __syncthreads();

    const float* w1e = d_w1c + (size_t)e * HDIM * CDIM;
    const float* w3e = d_w3c + (size_t)e * HDIM * CDIM;

    auto load_chunk = [&](int c, int st) {
        int k0 = c * BK;
#pragma unroll
        for (int t = 0; t < 4; t++) {                    // A: 1024 x 16B
            int i = tid + t * 256;
            int m = i >> 3, f4 = i & 7;
            int tok = s_tok[m];
            const float* src = (tok >= 0) ? &d_xc[(size_t)tok * CDIM + k0 + f4 * 4] : d_xc;
            cp16(sb + (G1_A(st) + m * 36 + f4 * 4) * 4, src, (tok >= 0) ? 16u : 0u);
        }
#pragma unroll
        for (int t = 0; t < 2; t++) {                    // B1/B3: 512 x 16B each
            int i = tid + t * 256;
            int nn = i >> 3, f4 = i & 7;
            int hr = n0 + nn;
            uint32_t ok = (hr < HDIM) ? 16u : 0u;
            const float* s1 = (hr < HDIM) ? &w1e[(size_t)hr * CDIM + k0 + f4 * 4] : w1e;
            const float* s3 = (hr < HDIM) ? &w3e[(size_t)hr * CDIM + k0 + f4 * 4] : w3e;
            cp16(sb + (G1_B1(st) + nn * 36 + f4 * 4) * 4, s1, ok);
            cp16(sb + (G1_B3(st) + nn * 36 + f4 * 4) * 4, s3, ok);
        }
    };

    float c1[2][4][4], c3[2][4][4];
#pragma unroll
    for (int mt = 0; mt < 2; mt++)
#pragma unroll
        for (int nt = 0; nt < 4; nt++)
#pragma unroll
            for (int r = 0; r < 4; r++) { c1[mt][nt][r] = 0.f; c3[mt][nt][r] = 0.f; }

    int lr = lane >> 2, lc = lane & 3;
    const int NC = CDIM / BK;   // 8

    load_chunk(0, 0);
    CP_COMMIT();

    for (int c = 0; c < NC; c++) {
        int st = c & 1;
        if (c + 1 < NC) { load_chunk(c + 1, st ^ 1); CP_COMMIT(); CP_WAIT(1); }
        else            { CP_WAIT(0); }
        __syncthreads();

        const float* As  = smem + G1_A(st);
        const float* B1s = smem + G1_B1(st);
        const float* B3s = smem + G1_B3(st);
#pragma unroll
        for (int ks = 0; ks < BK / 8; ks++) {
            int k = ks * 8;
            uint32_t a[2][4];
#pragma unroll
            for (int mt = 0; mt < 2; mt++) {
                int row = wm * 32 + mt * 16 + lr;
                a[mt][0] = __float_as_uint(As[row * 36 + k + lc]);
                a[mt][1] = __float_as_uint(As[(row + 8) * 36 + k + lc]);
                a[mt][2] = __float_as_uint(As[row * 36 + k + 4 + lc]);
                a[mt][3] = __float_as_uint(As[(row + 8) * 36 + k + 4 + lc]);
            }
#pragma unroll
            for (int nt = 0; nt < 4; nt++) {
                int col = wn * 32 + nt * 8 + lr;
                uint32_t b10 = __float_as_uint(B1s[col * 36 + k + lc]);
                uint32_t b11 = __float_as_uint(B1s[col * 36 + k + 4 + lc]);
                uint32_t b30 = __float_as_uint(B3s[col * 36 + k + lc]);
                uint32_t b31 = __float_as_uint(B3s[col * 36 + k + 4 + lc]);
#pragma unroll
                for (int mt = 0; mt < 2; mt++) {
                    mma_tf32(c1[mt][nt], a[mt][0], a[mt][1], a[mt][2], a[mt][3], b10, b11);
                    mma_tf32(c3[mt][nt], a[mt][0], a[mt][1], a[mt][2], a[mt][3], b30, b31);
                }
            }
        }
        __syncthreads();
    }

    // epilogue: h = silu(c1)*c3, pre-rounded to tf32 for GEMM2
#pragma unroll
    for (int mt = 0; mt < 2; mt++) {
#pragma unroll
        for (int nt = 0; nt < 4; nt++) {
#pragma unroll
            for (int half = 0; half < 2; half++) {
                int row = sbase + wm * 32 + mt * 16 + lr + half * 8;
                int col = n0 + wn * 32 + nt * 8 + lc * 2;
                float a0 = c1[mt][nt][half * 2 + 0], a1 = c1[mt][nt][half * 2 + 1];
                float b0 = c3[mt][nt][half * 2 + 0], b1 = c3[mt][nt][half * 2 + 1];
                float2 o;
                o.x = tf32f(a0 / (1.f + expf(-a0)) * b0);
                o.y = tf32f(a1 / (1.f + expf(-a1)) * b1);
                *(float2*)&d_h[(size_t)row * HPAD + col] = o;
            }
        }
    }
}

// ---------------- GEMM2: y = h w2^T ---------------------------------------
__global__ void __launch_bounds__(256) k_gemm2_mma() {
    extern __shared__ float smem[];
    uint32_t sb = smem_u32(smem);

    int sbase = blockIdx.x * TM;
    int total = d_poff[NEXP];
    if (sbase >= total) return;
    int e = 0;
#pragma unroll
    for (int q = 0; q < NEXP - 1; q++) if (d_poff[q + 1] <= sbase) e = q + 1;
    int n0 = blockIdx.y * TN;

    int tid = threadIdx.x, lane = tid & 31, wid = tid >> 5;
    int wm = wid >> 1, wn = wid & 1;
    const float* w2e = d_w2c + (size_t)e * CDIM * HDIM;

    auto load_chunk = [&](int c, int st) {
        int k0 = c * BK;
#pragma unroll
        for (int t = 0; t < 4; t++) {                    // A (d_h): 1024 x 16B
            int i = tid + t * 256;
            int m = i >> 3, f4 = i & 7;
            cp16(sb + (G2_A(st) + m * 36 + f4 * 4) * 4,
                 &d_h[(size_t)(sbase + m) * HPAD + k0 + f4 * 4], 16u);
        }
#pragma unroll
        for (int t = 0; t < 4; t++) {                    // B (w2 rows, 682): 1024 x 8B
            int i = tid + t * 256;
            int nn = i >> 4, f2 = i & 15;
            int kg = k0 + f2 * 2;
            const float* src = (kg < HDIM) ? &w2e[(size_t)(n0 + nn) * HDIM + kg] : w2e;
            cp8(sb + (G2_B(st) + nn * 36 + f2 * 2) * 4, src, (kg < HDIM) ? 8u : 0u);
        }
    };

    float cacc[2][4][4];
#pragma unroll
    for (int mt = 0; mt < 2; mt++)
#pragma unroll
        for (int nt = 0; nt < 4; nt++)
#pragma unroll
            for (int r = 0; r < 4; r++) cacc[mt][nt][r] = 0.f;

    int lr = lane >> 2, lc = lane & 3;
    const int NC = HPAD / BK;   // 22

    load_chunk(0, 0);
    CP_COMMIT();

    for (int c = 0; c < NC; c++) {
        int st = c & 1;
        if (c + 1 < NC) { load_chunk(c + 1, st ^ 1); CP_COMMIT(); CP_WAIT(1); }
        else            { CP_WAIT(0); }
        __syncthreads();

        const float* As = smem + G2_A(st);
        const float* Bs = smem + G2_B(st);
#pragma unroll
        for (int ks = 0; ks < BK / 8; ks++) {
            int k = ks * 8;
            uint32_t a[2][4];
#pragma unroll
            for (int mt = 0; mt < 2; mt++) {
                int row = wm * 32 + mt * 16 + lr;
                a[mt][0] = __float_as_uint(As[row * 36 + k + lc]);
                a[mt][1] = __float_as_uint(As[(row + 8) * 36 + k + lc]);
                a[mt][2] = __float_as_uint(As[row * 36 + k + 4 + lc]);
                a[mt][3] = __float_as_uint(As[(row + 8) * 36 + k + 4 + lc]);
            }
#pragma unroll
            for (int nt = 0; nt < 4; nt++) {
                int col = wn * 32 + nt * 8 + lr;
                uint32_t b0 = __float_as_uint(Bs[col * 36 + k + lc]);
                uint32_t b1 = __float_as_uint(Bs[col * 36 + k + 4 + lc]);
#pragma unroll
                for (int mt = 0; mt < 2; mt++)
                    mma_tf32(cacc[mt][nt], a[mt][0], a[mt][1], a[mt][2], a[mt][3], b0, b1);
            }
        }
        __syncthreads();
    }

#pragma unroll
    for (int mt = 0; mt < 2; mt++) {
#pragma unroll
        for (int nt = 0; nt < 4; nt++) {
#pragma unroll
            for (int half = 0; half < 2; half++) {
                int row = sbase + wm * 32 + mt * 16 + lr + half * 8;
                int col = n0 + wn * 32 + nt * 8 + lc * 2;
                float2 o = make_float2(cacc[mt][nt][half * 2 + 0], cacc[mt][nt][half * 2 + 1]);
                *(float2*)&d_yv[(size_t)row * CDIM + col] = o;
            }
        }
    }
}

// ---------------- combine ----------------
__global__ void k_combine(float* __restrict__ out) {
    int idx = blockIdx.x * blockDim.x + threadIdx.x;
    if (idx >= NTOK * (CDIM / 4)) return;
    int n = idx >> 6, c4 = idx & 63;
    int s0 = d_tok_slot[2 * n + 0], s1 = d_tok_slot[2 * n + 1];
    float g0 = d_tok_gate[2 * n + 0], g1 = d_tok_gate[2 * n + 1];
    float4 y0 = *(const float4*)&d_yv[(size_t)s0 * CDIM + c4 * 4];
    float4 y1 = *(const float4*)&d_yv[(size_t)s1 * CDIM + c4 * 4];
    float4 o;
    o.x = g0 * y0.x + g1 * y1.x;
    o.y = g0 * y0.y + g1 * y1.y;
    o.z = g0 * y0.z + g1 * y1.z;
    o.w = g0 * y0.w + g1 * y1.w;
    *(float4*)&out[(size_t)n * CDIM + c4 * 4] = o;
}

// ---------------- launch ----------------
extern "C" void kernel_launch(void* const* d_in, const int* in_sizes, int n_in,
                              void* d_out, int out_size) {
    const float* x  = (const float*)d_in[0];
    const float* rw = (const float*)d_in[1];
    const float* w1 = (const float*)d_in[2];
    const float* w2 = (const float*)d_in[3];
    const float* w3 = (const float*)d_in[4];
    float* out = (float*)d_out;

    cudaFuncSetAttribute(k_gemm1_mma, cudaFuncAttributeMaxDynamicSharedMemorySize, G1_BYTES);
    cudaFuncSetAttribute(k_gemm2_mma, cudaFuncAttributeMaxDynamicSharedMemorySize, G2_BYTES);

    k_zero<<<1, 32>>>();
    k_router<<<NTOK / 8, 256>>>(x, rw);
    k_cvt_w<<<(WELEM / 4 + 255) / 256, 256>>>(w1, w3, w2);
    k_init_slots<<<(PADDED_MAX + 255) / 256, 256>>>();
    k_setup<<<1, 32>>>();
    k_scatter<<<(NTOK * 2 + 255) / 256, 256>>>();

    dim3 g1(MTILES, HPAD / TN);              // 264 x 11
    k_gemm1_mma<<<g1, 256, G1_BYTES>>>();

    dim3 g2(MTILES, CDIM / TN);              // 264 x 4
    k_gemm2_mma<<<g2, 256, G2_BYTES>>>();

    k_combine<<<(NTOK * (CDIM / 4) + 255) / 256, 256>>>(out);
}

// round 6
// speedup vs baseline: 6.5389x; 1.0084x over previous
#include <cuda_runtime.h>
#include <math.h>
#include <stdint.h>

// Problem shapes (fixed)
#define NTOK 16384
#define CDIM 256
#define HDIM 682
#define HPAD 704            // 22 chunks of 32
#define NEXP 8
#define TM   128
#define BK   32
#define PADDED_MAX (NTOK*2 + NEXP*TM)   // 33792
#define MTILES (PADDED_MAX / TM)        // 264
#define WPELEM (NEXP * HPAD * CDIM)     // 1441792 (padded weight elems)

// ---------------- device scratch ----------------
__device__ int   d_counts[NEXP];
__device__ int   d_poff[NEXP + 1];
__device__ int   d_cursor[NEXP];
__device__ int   d_slot_token[PADDED_MAX];
__device__ int   d_tok_slot[NTOK * 2];
__device__ float d_tok_gate[NTOK * 2];
__device__ int   d_tok_expert[NTOK * 2];
__device__ float d_h[(size_t)PADDED_MAX * HPAD];
__device__ float d_yv[(size_t)PADDED_MAX * CDIM];
// tf32-prerounded, padded operand copies
__device__ float d_xc[(size_t)NTOK * CDIM];
__device__ float d_w1c[WPELEM];   // [E][HPAD][CDIM], rows >= HDIM zeroed
__device__ float d_w3c[WPELEM];   // [E][HPAD][CDIM]
__device__ float d_w2c[WPELEM];   // [E][CDIM][HPAD], cols >= HDIM zeroed

// ---------------- helpers ----------------
__device__ __forceinline__ uint32_t smem_u32(const void* p) {
    uint32_t a;
    asm("{ .reg .u64 t; cvta.to.shared.u64 t, %1; cvt.u32.u64 %0, t; }" : "=r"(a) : "l"(p));
    return a;
}
__device__ __forceinline__ float tf32f(float f) {
    uint32_t u;
    asm("cvt.rna.tf32.f32 %0, %1;" : "=r"(u) : "f"(f));
    return __uint_as_float(u);
}
__device__ __forceinline__ void mma_tf32(float c[4], uint32_t a0, uint32_t a1,
                                         uint32_t a2, uint32_t a3,
                                         uint32_t b0, uint32_t b1) {
    asm volatile(
        "mma.sync.aligned.m16n8k8.row.col.f32.tf32.tf32.f32 "
        "{%0,%1,%2,%3}, {%4,%5,%6,%7}, {%8,%9}, {%0,%1,%2,%3};"
        : "+f"(c[0]), "+f"(c[1]), "+f"(c[2]), "+f"(c[3])
        : "r"(a0), "r"(a1), "r"(a2), "r"(a3), "r"(b0), "r"(b1));
}
__device__ __forceinline__ void cp16(uint32_t dst, const void* src, uint32_t bytes) {
    asm volatile("cp.async.cg.shared.global [%0], [%1], 16, %2;"
                 :: "r"(dst), "l"(src), "r"(bytes) : "memory");
}
#define CP_COMMIT() asm volatile("cp.async.commit_group;" ::: "memory")
#define CP_WAIT(n)  asm volatile("cp.async.wait_group %0;" :: "n"(n) : "memory")

// SMEM float offsets, pitch 36 floats (144B) = conflict-free
#define G1_A(st)  ((st) * 4608)
#define G1_B1(st) (9216 + (st) * 2304)
#define G1_B3(st) (13824 + (st) * 2304)
#define G1_BYTES  73728
#define G2_A(st)  ((st) * 4608)
#define G2_B(st)  (9216 + (st) * 4608)
#define G2_BYTES  73728

// ---------------- k_prep: zero counts, init slots, pad+round weights -----
__global__ void k_prep(const float* __restrict__ w1, const float* __restrict__ w3,
                       const float* __restrict__ w2) {
    int i = blockIdx.x * blockDim.x + threadIdx.x;
    if (i < NEXP) d_counts[i] = 0;
    if (i < PADDED_MAX) d_slot_token[i] = -1;
    if (i >= WPELEM / 4) return;

    // w1/w3 -> [E][HPAD][CDIM]
    {
        int c4 = i & 63;
        int h  = (i >> 6) % HPAD;
        int e  = i / (64 * HPAD);
        float4 a = make_float4(0.f, 0.f, 0.f, 0.f), b = a;
        if (h < HDIM) {
            size_t off = ((size_t)e * HDIM + h) * CDIM + c4 * 4;
            a = *(const float4*)(w1 + off);
            b = *(const float4*)(w3 + off);
        }
        ((float4*)d_w1c)[i] = make_float4(tf32f(a.x), tf32f(a.y), tf32f(a.z), tf32f(a.w));
        ((float4*)d_w3c)[i] = make_float4(tf32f(b.x), tf32f(b.y), tf32f(b.z), tf32f(b.w));
    }
    // w2 -> [E][CDIM][HPAD]
    {
        int h4 = (i % 176) * 4;
        int c  = (i / 176) % CDIM;
        int e  = i / (176 * CDIM);
        const float* src = w2 + ((size_t)e * CDIM + c) * HDIM + h4;
        float4 v = make_float4(0.f, 0.f, 0.f, 0.f);
        if (h4 + 3 < HDIM) { v.x = src[0]; v.y = src[1]; v.z = src[2]; v.w = src[3]; }
        else {
            if (h4 + 0 < HDIM) v.x = src[0];
            if (h4 + 1 < HDIM) v.y = src[1];
        }
        ((float4*)d_w2c)[i] = make_float4(tf32f(v.x), tf32f(v.y), tf32f(v.z), tf32f(v.w));
    }
}

// ---------------- router ----------------
__global__ void k_router(const float* __restrict__ x, const float* __restrict__ rw) {
    __shared__ float s_rw[NEXP * CDIM];
    for (int i = threadIdx.x; i < NEXP * CDIM; i += blockDim.x) s_rw[i] = rw[i];
    __syncthreads();
    int warp = threadIdx.x >> 5, lane = threadIdx.x & 31;
    int n = blockIdx.x * 8 + warp;
    if (n >= NTOK) return;
    const float* xr = x + (size_t)n * CDIM;
    float acc[NEXP];
#pragma unroll
    for (int e = 0; e < NEXP; e++) acc[e] = 0.f;
    for (int c = lane; c < CDIM; c += 32) {
        float xv = xr[c];
        d_xc[(size_t)n * CDIM + c] = tf32f(xv);
#pragma unroll
        for (int e = 0; e < NEXP; e++) acc[e] = fmaf(xv, s_rw[e * CDIM + c], acc[e]);
    }
#pragma unroll
    for (int e = 0; e < NEXP; e++)
#pragma unroll
        for (int off = 16; off; off >>= 1)
            acc[e] += __shfl_down_sync(0xffffffffu, acc[e], off);
    if (lane != 0) return;
    float m = acc[0];
#pragma unroll
    for (int e = 1; e < NEXP; e++) m = fmaxf(m, acc[e]);
    float p[NEXP], s = 0.f;
#pragma unroll
    for (int e = 0; e < NEXP; e++) { p[e] = expf(acc[e] - m); s += p[e]; }
    float inv = 1.f / s;
#pragma unroll
    for (int e = 0; e < NEXP; e++) p[e] *= inv;
    int i0 = 0;
#pragma unroll
    for (int e = 1; e < NEXP; e++) if (p[e] > p[i0]) i0 = e;
    int i1 = (i0 == 0) ? 1 : 0;
#pragma unroll
    for (int e = 0; e < NEXP; e++) if (e != i0 && p[e] > p[i1]) i1 = e;
    float denom = p[i0] + p[i1] + 1e-9f;
    d_tok_expert[2 * n + 0] = i0;
    d_tok_expert[2 * n + 1] = i1;
    d_tok_gate[2 * n + 0] = p[i0] / denom;
    d_tok_gate[2 * n + 1] = p[i1] / denom;
    atomicAdd(&d_counts[i0], 1);
    atomicAdd(&d_counts[i1], 1);
}

__global__ void k_setup() {
    if (threadIdx.x == 0) {
        int off = 0;
        for (int e = 0; e < NEXP; e++) {
            d_poff[e] = off;
            d_cursor[e] = off;
            off += ((d_counts[e] + TM - 1) / TM) * TM;
        }
        d_poff[NEXP] = off;
    }
}

__global__ void k_scatter() {
    int i = blockIdx.x * blockDim.x + threadIdx.x;
    if (i >= NTOK * 2) return;
    int n = i >> 1;
    int e = d_tok_expert[i];
    int pos = atomicAdd(&d_cursor[e], 1);
    d_slot_token[pos] = n;
    d_tok_slot[i] = pos;
}

// ---------------- GEMM1: h = silu(x w1^T) * (x w3^T) ---------------------
// 128 thr = 4 warps (2M x 2N), warp tile 64x32, block 128x64.
__global__ void __launch_bounds__(128) k_gemm1_mma() {
    extern __shared__ float smem[];
    __shared__ int s_tok[TM];
    uint32_t sb = smem_u32(smem);

    int sbase = blockIdx.x * TM;
    if (sbase >= d_poff[NEXP]) return;
    int e = 0;
#pragma unroll
    for (int q = 0; q < NEXP - 1; q++) if (d_poff[q + 1] <= sbase) e = q + 1;
    int n0 = blockIdx.y * 64;

    int tid = threadIdx.x, lane = tid & 31, wid = tid >> 5;
    int wm = wid >> 1, wn = wid & 1;
    s_tok[tid] = d_slot_token[sbase + tid];
    __syncthreads();

    const float* w1e = d_w1c + (size_t)e * HPAD * CDIM;
    const float* w3e = d_w3c + (size_t)e * HPAD * CDIM;

    auto load_chunk = [&](int c, int st) {
        int k0 = c * BK;
#pragma unroll
        for (int t = 0; t < 8; t++) {                    // A: 1024 x 16B
            int i = tid + t * 128;
            int m = i >> 3, f4 = i & 7;
            int tok = s_tok[m];
            const float* src = (tok >= 0) ? &d_xc[(size_t)tok * CDIM + k0 + f4 * 4] : d_xc;
            cp16(sb + (G1_A(st) + m * 36 + f4 * 4) * 4, src, (tok >= 0) ? 16u : 0u);
        }
#pragma unroll
        for (int t = 0; t < 4; t++) {                    // B1/B3: 512 x 16B each
            int i = tid + t * 128;
            int nn = i >> 3, f4 = i & 7;
            size_t off = (size_t)(n0 + nn) * CDIM + k0 + f4 * 4;
            cp16(sb + (G1_B1(st) + nn * 36 + f4 * 4) * 4, w1e + off, 16u);
            cp16(sb + (G1_B3(st) + nn * 36 + f4 * 4) * 4, w3e + off, 16u);
        }
    };

    float c1[4][4][4], c3[4][4][4];
#pragma unroll
    for (int mt = 0; mt < 4; mt++)
#pragma unroll
        for (int nt = 0; nt < 4; nt++)
#pragma unroll
            for (int r = 0; r < 4; r++) { c1[mt][nt][r] = 0.f; c3[mt][nt][r] = 0.f; }

    int lr = lane >> 2, lc = lane & 3;
    const int NC = CDIM / BK;   // 8

    load_chunk(0, 0);
    CP_COMMIT();

    for (int c = 0; c < NC; c++) {
        int st = c & 1;
        if (c + 1 < NC) { load_chunk(c + 1, st ^ 1); CP_COMMIT(); CP_WAIT(1); }
        else            { CP_WAIT(0); }
        __syncthreads();

        const float* As  = smem + G1_A(st);
        const float* B1s = smem + G1_B1(st);
        const float* B3s = smem + G1_B3(st);
#pragma unroll
        for (int ks = 0; ks < BK / 8; ks++) {
            int k = ks * 8;
            uint32_t a[4][4];
#pragma unroll
            for (int mt = 0; mt < 4; mt++) {
                int row = wm * 64 + mt * 16 + lr;
                a[mt][0] = __float_as_uint(As[row * 36 + k + lc]);
                a[mt][1] = __float_as_uint(As[(row + 8) * 36 + k + lc]);
                a[mt][2] = __float_as_uint(As[row * 36 + k + 4 + lc]);
                a[mt][3] = __float_as_uint(As[(row + 8) * 36 + k + 4 + lc]);
            }
#pragma unroll
            for (int nt = 0; nt < 4; nt++) {
                int col = wn * 32 + nt * 8 + lr;
                uint32_t b10 = __float_as_uint(B1s[col * 36 + k + lc]);
                uint32_t b11 = __float_as_uint(B1s[col * 36 + k + 4 + lc]);
                uint32_t b30 = __float_as_uint(B3s[col * 36 + k + lc]);
                uint32_t b31 = __float_as_uint(B3s[col * 36 + k + 4 + lc]);
#pragma unroll
                for (int mt = 0; mt < 4; mt++) {
                    mma_tf32(c1[mt][nt], a[mt][0], a[mt][1], a[mt][2], a[mt][3], b10, b11);
                    mma_tf32(c3[mt][nt], a[mt][0], a[mt][1], a[mt][2], a[mt][3], b30, b31);
                }
            }
        }
        __syncthreads();
    }

    // epilogue: h = silu(c1)*c3 (tf32-rounded for GEMM2)
#pragma unroll
    for (int mt = 0; mt < 4; mt++) {
#pragma unroll
        for (int nt = 0; nt < 4; nt++) {
#pragma unroll
            for (int half = 0; half < 2; half++) {
                int row = sbase + wm * 64 + mt * 16 + lr + half * 8;
                int col = n0 + wn * 32 + nt * 8 + lc * 2;
                float a0 = c1[mt][nt][half * 2 + 0], a1 = c1[mt][nt][half * 2 + 1];
                float b0 = c3[mt][nt][half * 2 + 0], b1 = c3[mt][nt][half * 2 + 1];
                float2 o;
                o.x = tf32f(a0 / (1.f + expf(-a0)) * b0);
                o.y = tf32f(a1 / (1.f + expf(-a1)) * b1);
                *(float2*)&d_h[(size_t)row * HPAD + col] = o;
            }
        }
    }
}

// ---------------- GEMM2: y = h w2^T ---------------------------------------
// 128 thr = 4 warps (2M x 2N), warp tile 64x64, block 128x128.
__global__ void __launch_bounds__(128) k_gemm2_mma() {
    extern __shared__ float smem[];
    uint32_t sb = smem_u32(smem);

    int sbase = blockIdx.x * TM;
    if (sbase >= d_poff[NEXP]) return;
    int e = 0;
#pragma unroll
    for (int q = 0; q < NEXP - 1; q++) if (d_poff[q + 1] <= sbase) e = q + 1;
    int n0 = blockIdx.y * 128;

    int tid = threadIdx.x, lane = tid & 31, wid = tid >> 5;
    int wm = wid >> 1, wn = wid & 1;
    const float* w2e = d_w2c + (size_t)e * CDIM * HPAD;

    auto load_chunk = [&](int c, int st) {
        int k0 = c * BK;
#pragma unroll
        for (int t = 0; t < 8; t++) {                    // A (d_h): 1024 x 16B
            int i = tid + t * 128;
            int m = i >> 3, f4 = i & 7;
            cp16(sb + (G2_A(st) + m * 36 + f4 * 4) * 4,
                 &d_h[(size_t)(sbase + m) * HPAD + k0 + f4 * 4], 16u);
        }
#pragma unroll
        for (int t = 0; t < 8; t++) {                    // B (w2c padded): 1024 x 16B
            int i = tid + t * 128;
            int nn = i >> 3, f4 = i & 7;
            cp16(sb + (G2_B(st) + nn * 36 + f4 * 4) * 4,
                 &w2e[(size_t)(n0 + nn) * HPAD + k0 + f4 * 4], 16u);
        }
    };

    float cacc[4][8][4];
#pragma unroll
    for (int mt = 0; mt < 4; mt++)
#pragma unroll
        for (int nt = 0; nt < 8; nt++)
#pragma unroll
            for (int r = 0; r < 4; r++) cacc[mt][nt][r] = 0.f;

    int lr = lane >> 2, lc = lane & 3;
    const int NC = HPAD / BK;   // 22

    load_chunk(0, 0);
    CP_COMMIT();

    for (int c = 0; c < NC; c++) {
        int st = c & 1;
        if (c + 1 < NC) { load_chunk(c + 1, st ^ 1); CP_COMMIT(); CP_WAIT(1); }
        else            { CP_WAIT(0); }
        __syncthreads();

        const float* As = smem + G2_A(st);
        const float* Bs = smem + G2_B(st);
#pragma unroll
        for (int ks = 0; ks < BK / 8; ks++) {
            int k = ks * 8;
            uint32_t a[4][4];
#pragma unroll
            for (int mt = 0; mt < 4; mt++) {
                int row = wm * 64 + mt * 16 + lr;
                a[mt][0] = __float_as_uint(As[row * 36 + k + lc]);
                a[mt][1] = __float_as_uint(As[(row + 8) * 36 + k + lc]);
                a[mt][2] = __float_as_uint(As[row * 36 + k + 4 + lc]);
                a[mt][3] = __float_as_uint(As[(row + 8) * 36 + k + 4 + lc]);
            }
#pragma unroll
            for (int nt = 0; nt < 8; nt++) {
                int col = wn * 64 + nt * 8 + lr;
                uint32_t b0 = __float_as_uint(Bs[col * 36 + k + lc]);
                uint32_t b1 = __float_as_uint(Bs[col * 36 + k + 4 + lc]);
#pragma unroll
                for (int mt = 0; mt < 4; mt++)
                    mma_tf32(cacc[mt][nt], a[mt][0], a[mt][1], a[mt][2], a[mt][3], b0, b1);
            }
        }
        __syncthreads();
    }

#pragma unroll
    for (int mt = 0; mt < 4; mt++) {
#pragma unroll
        for (int nt = 0; nt < 8; nt++) {
#pragma unroll
            for (int half = 0; half < 2; half++) {
                int row = sbase + wm * 64 + mt * 16 + lr + half * 8;
                int col = n0 + wn * 64 + nt * 8 + lc * 2;
                float2 o = make_float2(cacc[mt][nt][half * 2 + 0], cacc[mt][nt][half * 2 + 1]);
                *(float2*)&d_yv[(size_t)row * CDIM + col] = o;
            }
        }
    }
}

// ---------------- combine ----------------
__global__ void k_combine(float* __restrict__ out) {
    int idx = blockIdx.x * blockDim.x + threadIdx.x;
    if (idx >= NTOK * (CDIM / 4)) return;
    int n = idx >> 6, c4 = idx & 63;
    int s0 = d_tok_slot[2 * n + 0], s1 = d_tok_slot[2 * n + 1];
    float g0 = d_tok_gate[2 * n + 0], g1 = d_tok_gate[2 * n + 1];
    float4 y0 = *(const float4*)&d_yv[(size_t)s0 * CDIM + c4 * 4];
    float4 y1 = *(const float4*)&d_yv[(size_t)s1 * CDIM + c4 * 4];
    float4 o;
    o.x = g0 * y0.x + g1 * y1.x;
    o.y = g0 * y0.y + g1 * y1.y;
    o.z = g0 * y0.z + g1 * y1.z;
    o.w = g0 * y0.w + g1 * y1.w;
    *(float4*)&out[(size_t)n * CDIM + c4 * 4] = o;
}

// ---------------- launch ----------------
extern "C" void kernel_launch(void* const* d_in, const int* in_sizes, int n_in,
                              void* d_out, int out_size) {
    const float* x  = (const float*)d_in[0];
    const float* rw = (const float*)d_in[1];
    const float* w1 = (const float*)d_in[2];
    const float* w2 = (const float*)d_in[3];
    const float* w3 = (const float*)d_in[4];
    float* out = (float*)d_out;

    cudaFuncSetAttribute(k_gemm1_mma, cudaFuncAttributeMaxDynamicSharedMemorySize, G1_BYTES);
    cudaFuncSetAttribute(k_gemm2_mma, cudaFuncAttributeMaxDynamicSharedMemorySize, G2_BYTES);

    k_prep<<<(WPELEM / 4 + 255) / 256, 256>>>(w1, w3, w2);
    k_router<<<NTOK / 8, 256>>>(x, rw);
    k_setup<<<1, 32>>>();
    k_scatter<<<(NTOK * 2 + 255) / 256, 256>>>();

    dim3 g1(MTILES, HPAD / 64);              // 264 x 11
    k_gemm1_mma<<<g1, 128, G1_BYTES>>>();

    dim3 g2(MTILES, CDIM / 128);             // 264 x 2
    k_gemm2_mma<<<g2, 128, G2_BYTES>>>();

    k_combine<<<(NTOK * (CDIM / 4) + 255) / 256, 256>>>(out);
}

// round 7
// speedup vs baseline: 9.3028x; 1.4227x over previous
#include <cuda_runtime.h>
#include <cuda_fp16.h>
#include <math.h>
#include <stdint.h>

// Problem shapes (fixed)
#define NTOK 16384
#define CDIM 256
#define HDIM 682
#define HPAD 704            // 22 chunks of 32
#define NEXP 8
#define TM   128
#define BK   32
#define PADDED_MAX (NTOK*2 + NEXP*TM)   // 33792
#define MTILES (PADDED_MAX / TM)        // 264
#define WPELEM (NEXP * HPAD * CDIM)     // 1441792

// ---------------- device scratch ----------------
__device__ int    d_counts[NEXP];
__device__ int    d_poff[NEXP + 1];
__device__ int    d_cursor[NEXP];
__device__ int    d_slot_token[PADDED_MAX];
__device__ int    d_tok_slot[NTOK * 2];
__device__ float  d_tok_gate[NTOK * 2];
__device__ int    d_tok_expert[NTOK * 2];
__device__ __half d_h[(size_t)PADDED_MAX * HPAD];
__device__ float  d_yv[(size_t)PADDED_MAX * CDIM];
// fp16 operand copies
__device__ __half d_xc[(size_t)NTOK * CDIM];
__device__ __half d_w1c[WPELEM];   // [E][HPAD][CDIM]
__device__ __half d_w3c[WPELEM];   // [E][HPAD][CDIM]
__device__ __half d_w2c[WPELEM];   // [E][CDIM][HPAD]

// ---------------- helpers ----------------
__device__ __forceinline__ uint32_t smem_u32(const void* p) {
    uint32_t a;
    asm("{ .reg .u64 t; cvta.to.shared.u64 t, %1; cvt.u32.u64 %0, t; }" : "=r"(a) : "l"(p));
    return a;
}
__device__ __forceinline__ void mma_fp16(float c[4], uint32_t a0, uint32_t a1,
                                         uint32_t a2, uint32_t a3,
                                         uint32_t b0, uint32_t b1) {
    asm volatile(
        "mma.sync.aligned.m16n8k16.row.col.f32.f16.f16.f32 "
        "{%0,%1,%2,%3}, {%4,%5,%6,%7}, {%8,%9}, {%0,%1,%2,%3};"
        : "+f"(c[0]), "+f"(c[1]), "+f"(c[2]), "+f"(c[3])
        : "r"(a0), "r"(a1), "r"(a2), "r"(a3), "r"(b0), "r"(b1));
}
__device__ __forceinline__ void cp16(uint32_t dst, const void* src, uint32_t bytes) {
    asm volatile("cp.async.cg.shared.global [%0], [%1], 16, %2;"
                 :: "r"(dst), "l"(src), "r"(bytes) : "memory");
}
#define CP_COMMIT() asm volatile("cp.async.commit_group;" ::: "memory")
#define CP_WAIT(n)  asm volatile("cp.async.wait_group %0;" :: "n"(n) : "memory")

// SMEM offsets in HALF units, pitch 40 halves (80B) -> conflict-free
#define PITCH 40
#define G1_A(st)  ((st) * 5120)
#define G1_B1(st) (10240 + (st) * 2560)
#define G1_B3(st) (15360 + (st) * 2560)
#define G1_BYTES  40960
#define G2_A(st)  ((st) * 5120)
#define G2_B(st)  (10240 + (st) * 5120)
#define G2_BYTES  40960

// ---------------- k_prep: counts, slots, weight convert/pad --------------
__global__ void k_prep(const float* __restrict__ w1, const float* __restrict__ w3,
                       const float* __restrict__ w2) {
    int i = blockIdx.x * blockDim.x + threadIdx.x;
    if (i < NEXP) d_counts[i] = 0;
    if (i < PADDED_MAX) d_slot_token[i] = -1;
    if (i >= WPELEM / 4) return;

    // w1/w3 -> half [E][HPAD][CDIM]
    {
        int c4 = i & 63;
        int h  = (i >> 6) % HPAD;
        int e  = i / (64 * HPAD);
        float4 a = make_float4(0.f, 0.f, 0.f, 0.f), b = a;
        if (h < HDIM) {
            size_t off = ((size_t)e * HDIM + h) * CDIM + c4 * 4;
            a = *(const float4*)(w1 + off);
            b = *(const float4*)(w3 + off);
        }
        __half2* p1 = (__half2*)&d_w1c[(size_t)i * 4];
        __half2* p3 = (__half2*)&d_w3c[(size_t)i * 4];
        p1[0] = __floats2half2_rn(a.x, a.y); p1[1] = __floats2half2_rn(a.z, a.w);
        p3[0] = __floats2half2_rn(b.x, b.y); p3[1] = __floats2half2_rn(b.z, b.w);
    }
    // w2 -> half [E][CDIM][HPAD]
    {
        int h4 = (i % 176) * 4;
        int c  = (i / 176) % CDIM;
        int e  = i / (176 * CDIM);
        const float* src = w2 + ((size_t)e * CDIM + c) * HDIM + h4;
        float4 v = make_float4(0.f, 0.f, 0.f, 0.f);
        if (h4 + 3 < HDIM) { v.x = src[0]; v.y = src[1]; v.z = src[2]; v.w = src[3]; }
        else {
            if (h4 + 0 < HDIM) v.x = src[0];
            if (h4 + 1 < HDIM) v.y = src[1];
        }
        __half2* p2 = (__half2*)&d_w2c[(size_t)i * 4];
        p2[0] = __floats2half2_rn(v.x, v.y); p2[1] = __floats2half2_rn(v.z, v.w);
    }
}

// ---------------- router (fp32 math, writes fp16 x copy) -----------------
__global__ void k_router(const float* __restrict__ x, const float* __restrict__ rw) {
    __shared__ float s_rw[NEXP * CDIM];
    for (int i = threadIdx.x; i < NEXP * CDIM; i += blockDim.x) s_rw[i] = rw[i];
    __syncthreads();
    int warp = threadIdx.x >> 5, lane = threadIdx.x & 31;
    int n = blockIdx.x * 8 + warp;
    if (n >= NTOK) return;
    const float* xr = x + (size_t)n * CDIM;
    float acc[NEXP];
#pragma unroll
    for (int e = 0; e < NEXP; e++) acc[e] = 0.f;
    for (int c = lane; c < CDIM; c += 32) {
        float xv = xr[c];
        d_xc[(size_t)n * CDIM + c] = __float2half_rn(xv);
#pragma unroll
        for (int e = 0; e < NEXP; e++) acc[e] = fmaf(xv, s_rw[e * CDIM + c], acc[e]);
    }
#pragma unroll
    for (int e = 0; e < NEXP; e++)
#pragma unroll
        for (int off = 16; off; off >>= 1)
            acc[e] += __shfl_down_sync(0xffffffffu, acc[e], off);
    if (lane != 0) return;
    float m = acc[0];
#pragma unroll
    for (int e = 1; e < NEXP; e++) m = fmaxf(m, acc[e]);
    float p[NEXP], s = 0.f;
#pragma unroll
    for (int e = 0; e < NEXP; e++) { p[e] = expf(acc[e] - m); s += p[e]; }
    float inv = 1.f / s;
#pragma unroll
    for (int e = 0; e < NEXP; e++) p[e] *= inv;
    int i0 = 0;
#pragma unroll
    for (int e = 1; e < NEXP; e++) if (p[e] > p[i0]) i0 = e;
    int i1 = (i0 == 0) ? 1 : 0;
#pragma unroll
    for (int e = 0; e < NEXP; e++) if (e != i0 && p[e] > p[i1]) i1 = e;
    float denom = p[i0] + p[i1] + 1e-9f;
    d_tok_expert[2 * n + 0] = i0;
    d_tok_expert[2 * n + 1] = i1;
    d_tok_gate[2 * n + 0] = p[i0] / denom;
    d_tok_gate[2 * n + 1] = p[i1] / denom;
    atomicAdd(&d_counts[i0], 1);
    atomicAdd(&d_counts[i1], 1);
}

__global__ void k_setup() {
    if (threadIdx.x == 0) {
        int off = 0;
        for (int e = 0; e < NEXP; e++) {
            d_poff[e] = off;
            d_cursor[e] = off;
            off += ((d_counts[e] + TM - 1) / TM) * TM;
        }
        d_poff[NEXP] = off;
    }
}

__global__ void k_scatter() {
    int i = blockIdx.x * blockDim.x + threadIdx.x;
    if (i >= NTOK * 2) return;
    int n = i >> 1;
    int e = d_tok_expert[i];
    int pos = atomicAdd(&d_cursor[e], 1);
    d_slot_token[pos] = n;
    d_tok_slot[i] = pos;
}

// ---------------- GEMM1: h = silu(x w1^T) * (x w3^T)  (fp16 mma) ---------
// 128 thr = 4 warps (2M x 2N), warp tile 64x32, block 128x64.
__global__ void __launch_bounds__(128) k_gemm1_mma() {
    extern __shared__ __half smh[];
    __shared__ int s_tok[TM];
    uint32_t sb = smem_u32(smh);

    int sbase = blockIdx.x * TM;
    if (sbase >= d_poff[NEXP]) return;
    int e = 0;
#pragma unroll
    for (int q = 0; q < NEXP - 1; q++) if (d_poff[q + 1] <= sbase) e = q + 1;
    int n0 = blockIdx.y * 64;

    int tid = threadIdx.x, lane = tid & 31, wid = tid >> 5;
    int wm = wid >> 1, wn = wid & 1;
    s_tok[tid] = d_slot_token[sbase + tid];
    __syncthreads();

    const __half* w1e = d_w1c + (size_t)e * HPAD * CDIM;
    const __half* w3e = d_w3c + (size_t)e * HPAD * CDIM;

    auto load_chunk = [&](int c, int st) {
        int k0 = c * BK;
#pragma unroll
        for (int t = 0; t < 4; t++) {                    // A: 512 x 16B
            int i = tid + t * 128;
            int m = i >> 2, f4 = i & 3;
            int tok = s_tok[m];
            const __half* src = (tok >= 0) ? &d_xc[(size_t)tok * CDIM + k0 + f4 * 8] : d_xc;
            cp16(sb + (G1_A(st) + m * PITCH + f4 * 8) * 2, src, (tok >= 0) ? 16u : 0u);
        }
#pragma unroll
        for (int t = 0; t < 2; t++) {                    // B1/B3: 256 x 16B each
            int i = tid + t * 128;
            int nn = i >> 2, f4 = i & 3;
            size_t off = (size_t)(n0 + nn) * CDIM + k0 + f4 * 8;
            cp16(sb + (G1_B1(st) + nn * PITCH + f4 * 8) * 2, w1e + off, 16u);
            cp16(sb + (G1_B3(st) + nn * PITCH + f4 * 8) * 2, w3e + off, 16u);
        }
    };

    float c1[4][4][4], c3[4][4][4];
#pragma unroll
    for (int mt = 0; mt < 4; mt++)
#pragma unroll
        for (int nt = 0; nt < 4; nt++)
#pragma unroll
            for (int r = 0; r < 4; r++) { c1[mt][nt][r] = 0.f; c3[mt][nt][r] = 0.f; }

    int lr = lane >> 2, lc = lane & 3;
    const int NC = CDIM / BK;   // 8

    load_chunk(0, 0);
    CP_COMMIT();

    for (int c = 0; c < NC; c++) {
        int st = c & 1;
        if (c + 1 < NC) { load_chunk(c + 1, st ^ 1); CP_COMMIT(); CP_WAIT(1); }
        else            { CP_WAIT(0); }
        __syncthreads();

        const __half* As  = smh + G1_A(st);
        const __half* B1s = smh + G1_B1(st);
        const __half* B3s = smh + G1_B3(st);
#pragma unroll
        for (int ks = 0; ks < 2; ks++) {
            int k = ks * 16;
            uint32_t a[4][4];
#pragma unroll
            for (int mt = 0; mt < 4; mt++) {
                int row = wm * 64 + mt * 16 + lr;
                a[mt][0] = *(const uint32_t*)&As[row * PITCH + k + lc * 2];
                a[mt][1] = *(const uint32_t*)&As[(row + 8) * PITCH + k + lc * 2];
                a[mt][2] = *(const uint32_t*)&As[row * PITCH + k + 8 + lc * 2];
                a[mt][3] = *(const uint32_t*)&As[(row + 8) * PITCH + k + 8 + lc * 2];
            }
#pragma unroll
            for (int nt = 0; nt < 4; nt++) {
                int col = wn * 32 + nt * 8 + lr;
                uint32_t b10 = *(const uint32_t*)&B1s[col * PITCH + k + lc * 2];
                uint32_t b11 = *(const uint32_t*)&B1s[col * PITCH + k + 8 + lc * 2];
                uint32_t b30 = *(const uint32_t*)&B3s[col * PITCH + k + lc * 2];
                uint32_t b31 = *(const uint32_t*)&B3s[col * PITCH + k + 8 + lc * 2];
#pragma unroll
                for (int mt = 0; mt < 4; mt++) {
                    mma_fp16(c1[mt][nt], a[mt][0], a[mt][1], a[mt][2], a[mt][3], b10, b11);
                    mma_fp16(c3[mt][nt], a[mt][0], a[mt][1], a[mt][2], a[mt][3], b30, b31);
                }
            }
        }
        __syncthreads();
    }

    // epilogue: h = silu(c1)*c3 -> half
#pragma unroll
    for (int mt = 0; mt < 4; mt++) {
#pragma unroll
        for (int nt = 0; nt < 4; nt++) {
#pragma unroll
            for (int half = 0; half < 2; half++) {
                int row = sbase + wm * 64 + mt * 16 + lr + half * 8;
                int col = n0 + wn * 32 + nt * 8 + lc * 2;
                float a0 = c1[mt][nt][half * 2 + 0], a1 = c1[mt][nt][half * 2 + 1];
                float b0 = c3[mt][nt][half * 2 + 0], b1 = c3[mt][nt][half * 2 + 1];
                float h0 = a0 / (1.f + expf(-a0)) * b0;
                float h1 = a1 / (1.f + expf(-a1)) * b1;
                *(__half2*)&d_h[(size_t)row * HPAD + col] = __floats2half2_rn(h0, h1);
            }
        }
    }
}

// ---------------- GEMM2: y = h w2^T  (fp16 mma) --------------------------
// 128 thr = 4 warps (2M x 2N), warp tile 64x64, block 128x128.
__global__ void __launch_bounds__(128) k_gemm2_mma() {
    extern __shared__ __half smh[];
    uint32_t sb = smem_u32(smh);

    int sbase = blockIdx.x * TM;
    if (sbase >= d_poff[NEXP]) return;
    int e = 0;
#pragma unroll
    for (int q = 0; q < NEXP - 1; q++) if (d_poff[q + 1] <= sbase) e = q + 1;
    int n0 = blockIdx.y * 128;

    int tid = threadIdx.x, lane = tid & 31, wid = tid >> 5;
    int wm = wid >> 1, wn = wid & 1;
    const __half* w2e = d_w2c + (size_t)e * CDIM * HPAD;

    auto load_chunk = [&](int c, int st) {
        int k0 = c * BK;
#pragma unroll
        for (int t = 0; t < 4; t++) {                    // A (d_h): 512 x 16B
            int i = tid + t * 128;
            int m = i >> 2, f4 = i & 3;
            cp16(sb + (G2_A(st) + m * PITCH + f4 * 8) * 2,
                 &d_h[(size_t)(sbase + m) * HPAD + k0 + f4 * 8], 16u);
        }
#pragma unroll
        for (int t = 0; t < 4; t++) {                    // B (w2c): 512 x 16B
            int i = tid + t * 128;
            int nn = i >> 2, f4 = i & 3;
            cp16(sb + (G2_B(st) + nn * PITCH + f4 * 8) * 2,
                 &w2e[(size_t)(n0 + nn) * HPAD + k0 + f4 * 8], 16u);
        }
    };

    float cacc[4][8][4];
#pragma unroll
    for (int mt = 0; mt < 4; mt++)
#pragma unroll
        for (int nt = 0; nt < 8; nt++)
#pragma unroll
            for (int r = 0; r < 4; r++) cacc[mt][nt][r] = 0.f;

    int lr = lane >> 2, lc = lane & 3;
    const int NC = HPAD / BK;   // 22

    load_chunk(0, 0);
    CP_COMMIT();

    for (int c = 0; c < NC; c++) {
        int st = c & 1;
        if (c + 1 < NC) { load_chunk(c + 1, st ^ 1); CP_COMMIT(); CP_WAIT(1); }
        else            { CP_WAIT(0); }
        __syncthreads();

        const __half* As = smh + G2_A(st);
        const __half* Bs = smh + G2_B(st);
#pragma unroll
        for (int ks = 0; ks < 2; ks++) {
            int k = ks * 16;
            uint32_t a[4][4];
#pragma unroll
            for (int mt = 0; mt < 4; mt++) {
                int row = wm * 64 + mt * 16 + lr;
                a[mt][0] = *(const uint32_t*)&As[row * PITCH + k + lc * 2];
                a[mt][1] = *(const uint32_t*)&As[(row + 8) * PITCH + k + lc * 2];
                a[mt][2] = *(const uint32_t*)&As[row * PITCH + k + 8 + lc * 2];
                a[mt][3] = *(const uint32_t*)&As[(row + 8) * PITCH + k + 8 + lc * 2];
            }
#pragma unroll
            for (int nt = 0; nt < 8; nt++) {
                int col = wn * 64 + nt * 8 + lr;
                uint32_t b0 = *(const uint32_t*)&Bs[col * PITCH + k + lc * 2];
                uint32_t b1 = *(const uint32_t*)&Bs[col * PITCH + k + 8 + lc * 2];
#pragma unroll
                for (int mt = 0; mt < 4; mt++)
                    mma_fp16(cacc[mt][nt], a[mt][0], a[mt][1], a[mt][2], a[mt][3], b0, b1);
            }
        }
        __syncthreads();
    }

#pragma unroll
    for (int mt = 0; mt < 4; mt++) {
#pragma unroll
        for (int nt = 0; nt < 8; nt++) {
#pragma unroll
            for (int half = 0; half < 2; half++) {
                int row = sbase + wm * 64 + mt * 16 + lr + half * 8;
                int col = n0 + wn * 64 + nt * 8 + lc * 2;
                float2 o = make_float2(cacc[mt][nt][half * 2 + 0], cacc[mt][nt][half * 2 + 1]);
                *(float2*)&d_yv[(size_t)row * CDIM + col] = o;
            }
        }
    }
}

// ---------------- combine ----------------
__global__ void k_combine(float* __restrict__ out) {
    int idx = blockIdx.x * blockDim.x + threadIdx.x;
    if (idx >= NTOK * (CDIM / 4)) return;
    int n = idx >> 6, c4 = idx & 63;
    int s0 = d_tok_slot[2 * n + 0], s1 = d_tok_slot[2 * n + 1];
    float g0 = d_tok_gate[2 * n + 0], g1 = d_tok_gate[2 * n + 1];
    float4 y0 = *(const float4*)&d_yv[(size_t)s0 * CDIM + c4 * 4];
    float4 y1 = *(const float4*)&d_yv[(size_t)s1 * CDIM + c4 * 4];
    float4 o;
    o.x = g0 * y0.x + g1 * y1.x;
    o.y = g0 * y0.y + g1 * y1.y;
    o.z = g0 * y0.z + g1 * y1.z;
    o.w = g0 * y0.w + g1 * y1.w;
    *(float4*)&out[(size_t)n * CDIM + c4 * 4] = o;
}

// ---------------- launch ----------------
extern "C" void kernel_launch(void* const* d_in, const int* in_sizes, int n_in,
                              void* d_out, int out_size) {
    const float* x  = (const float*)d_in[0];
    const float* rw = (const float*)d_in[1];
    const float* w1 = (const float*)d_in[2];
    const float* w2 = (const float*)d_in[3];
    const float* w3 = (const float*)d_in[4];
    float* out = (float*)d_out;

    cudaFuncSetAttribute(k_gemm1_mma, cudaFuncAttributeMaxDynamicSharedMemorySize, G1_BYTES);
    cudaFuncSetAttribute(k_gemm2_mma, cudaFuncAttributeMaxDynamicSharedMemorySize, G2_BYTES);

    k_prep<<<(WPELEM / 4 + 255) / 256, 256>>>(w1, w3, w2);
    k_router<<<NTOK / 8, 256>>>(x, rw);
    k_setup<<<1, 32>>>();
    k_scatter<<<(NTOK * 2 + 255) / 256, 256>>>();

    dim3 g1(MTILES, HPAD / 64);              // 264 x 11
    k_gemm1_mma<<<g1, 128, G1_BYTES>>>();

    dim3 g2(MTILES, CDIM / 128);             // 264 x 2
    k_gemm2_mma<<<g2, 128, G2_BYTES>>>();

    k_combine<<<(NTOK * (CDIM / 4) + 255) / 256, 256>>>(out);
}